// round 14
// baseline (speedup 1.0000x reference)
#include <cuda_runtime.h>
#include <cstdint>
#include <math_constants.h>

// Problem constants (fixed instance)
#define BSZ   16
#define DIM   4096
#define NH    32
#define NKV   8
#define HD    128
#define MSL   4096
// start_pos = 4095, seqlen = 1

typedef unsigned long long ull;

// ---------------- packed fp32x2 helpers (Blackwell) ----------------
__device__ __forceinline__ ull f2fma(ull a, ull b, ull c) {
    ull d; asm("fma.rn.f32x2 %0, %1, %2, %3;" : "=l"(d) : "l"(a), "l"(b), "l"(c)); return d;
}
__device__ __forceinline__ ull f2add(ull a, ull b) {
    ull d; asm("add.rn.f32x2 %0, %1, %2;" : "=l"(d) : "l"(a), "l"(b)); return d;
}
__device__ __forceinline__ ull pack2(float lo, float hi) {
    ull r; asm("mov.b64 %0, {%1, %2};" : "=l"(r) : "f"(lo), "f"(hi)); return r;
}
__device__ __forceinline__ float2 unp2(ull v) {
    float lo, hi; asm("mov.b64 {%0, %1}, %2;" : "=f"(lo), "=f"(hi) : "l"(v));
    return make_float2(lo, hi);
}

// ---------------- scratch (no allocation allowed) ----------------
__device__ float g_q [BSZ * DIM];        // roped Q   [b][head*128+d]
__device__ float g_kn[BSZ * NKV * HD];   // roped new K [b][kv*128+d]
__device__ float g_vn[BSZ * NKV * HD];   // new V       [b][kv*128+d]
__device__ float g_ao[BSZ * DIM];        // attention out [b][head*128+d]

__device__ __forceinline__ void cp_async16(void* dst, const void* src) {
    uint32_t d = (uint32_t)__cvta_generic_to_shared(dst);
    asm volatile("cp.async.cg.shared.global [%0], [%1], 16;" :: "r"(d), "l"(src) : "memory");
}
__device__ __forceinline__ void cp_commit() {
    asm volatile("cp.async.commit_group;" ::: "memory");
}

// =================================================================
// GEMV core: 4 warps x 4 rows = 16 rows/CTA (128 threads), 16 batches.
// (unchanged from R11 — proven)
// =================================================================
__device__ __forceinline__ void gemv_r4(const float* __restrict__ xg,   // [16][4096]
                                        const float* __restrict__ Wr,  // 4-row base, stride DIM
                                        float4* lo, float4* hi,        // smem 2048 f4 each
                                        ull acc[32])
{
    const int tid  = threadIdx.x;     // 0..127
    const int lane = tid & 31;

#pragma unroll
    for (int i = 0; i < 32; ++i) acc[i] = 0ull;

    for (int c = 0; c < 4; ++c) {
        __syncthreads();              // previous chunk fully consumed
#pragma unroll
        for (int k = 0; k < 16; ++k) {
            int idx = (k << 7) + tid;     // 0..2047
            int bp  = idx >> 8;           // 0..7
            int q   = idx & 255;
            const float* p0 = xg + (size_t)(2 * bp) * DIM + (c << 10) + (q << 2);
            float4 f0 = *(const float4*)p0;
            float4 f1 = *(const float4*)(p0 + DIM);
            lo[(bp << 8) + q] = make_float4(f0.x, f1.x, f0.y, f1.y);
            hi[(bp << 8) + q] = make_float4(f0.z, f1.z, f0.w, f1.w);
        }
        __syncthreads();

        const float4* W4 = (const float4*)Wr + (c << 8);   // row stride 1024 f4
#pragma unroll
        for (int it = 0; it < 8; ++it) {
            int q = (it << 5) + lane;
            float4 w0 = W4[0 * 1024 + q];
            float4 w1 = W4[1 * 1024 + q];
            float4 w2 = W4[2 * 1024 + q];
            float4 w3 = W4[3 * 1024 + q];
            ull wp[16];
            wp[0]  = pack2(w0.x, w0.x); wp[1]  = pack2(w0.y, w0.y);
            wp[2]  = pack2(w0.z, w0.z); wp[3]  = pack2(w0.w, w0.w);
            wp[4]  = pack2(w1.x, w1.x); wp[5]  = pack2(w1.y, w1.y);
            wp[6]  = pack2(w1.z, w1.z); wp[7]  = pack2(w1.w, w1.w);
            wp[8]  = pack2(w2.x, w2.x); wp[9]  = pack2(w2.y, w2.y);
            wp[10] = pack2(w2.z, w2.z); wp[11] = pack2(w2.w, w2.w);
            wp[12] = pack2(w3.x, w3.x); wp[13] = pack2(w3.y, w3.y);
            wp[14] = pack2(w3.z, w3.z); wp[15] = pack2(w3.w, w3.w);
#pragma unroll
            for (int bp = 0; bp < 8; ++bp) {
                ulonglong2 e0 = *(const ulonglong2*)&lo[(bp << 8) + q];  // LDS.128
                ulonglong2 e1 = *(const ulonglong2*)&hi[(bp << 8) + q];
#pragma unroll
                for (int r = 0; r < 4; ++r) {
                    acc[r * 8 + bp] = f2fma(wp[r * 4 + 0], e0.x, acc[r * 8 + bp]);
                    acc[r * 8 + bp] = f2fma(wp[r * 4 + 1], e0.y, acc[r * 8 + bp]);
                    acc[r * 8 + bp] = f2fma(wp[r * 4 + 2], e1.x, acc[r * 8 + bp]);
                    acc[r * 8 + bp] = f2fma(wp[r * 4 + 3], e1.y, acc[r * 8 + bp]);
                }
            }
        }
    }
    // distributed log-reduce: lane L ends with total of acc[L] in acc[0]
#pragma unroll
    for (int o = 16; o >= 1; o >>= 1) {
#pragma unroll
        for (int jj = 0; jj < o; ++jj) {
            bool hb = (lane & o) != 0;
            ull keep = hb ? acc[jj + o] : acc[jj];
            ull send = hb ? acc[jj]     : acc[jj + o];
            acc[jj] = f2add(keep, __shfl_xor_sync(0xffffffffu, send, o));
        }
    }
}

// =================================================================
// Stage 1: Q/K/V projections + RoPE.  (unchanged from R11)
// =================================================================
__global__ __launch_bounds__(128, 3)
void qkv_kernel(const float* __restrict__ x,
                const float* __restrict__ wq,
                const float* __restrict__ wk,
                const float* __restrict__ wv,
                const float* __restrict__ fc,
                const float* __restrict__ fs)
{
    extern __shared__ float4 xsm[];
    float4* lo = xsm;
    float4* hi = xsm + 2048;
    const int warp = threadIdx.x >> 5;
    const int lane = threadIdx.x & 31;
    const int r0   = blockIdx.x * 16 + warp * 4;      // multiple of 4

    const float* W; int e0; int kind;
    if (r0 < 4096)      { W = wq; e0 = r0;        kind = 0; }
    else if (r0 < 5120) { W = wk; e0 = r0 - 4096; kind = 1; }
    else                { W = wv; e0 = r0 - 5120; kind = 2; }

    ull acc[32];
    gemv_r4(x, W + (size_t)e0 * DIM, lo, hi, acc);

    ull partn = __shfl_xor_sync(0xffffffffu, acc[0], 8);   // row r^1
    int r  = lane >> 3;
    int bp = lane & 7;
    int b0 = 2 * bp, b1 = 2 * bp + 1;
    int er = e0 + r;
    if (kind == 2) {
        float2 v = unp2(acc[0]);
        g_vn[b0 * 1024 + er] = v.x;
        g_vn[b1 * 1024 + er] = v.y;
    } else if (!(lane & 8)) {        // r even: rows er, er+1 form a RoPE pair
        float2 a  = unp2(acc[0]);    // even row
        float2 bb = unp2(partn);     // odd row
        int i = (er & 127) >> 1;
        float cc = fc[i], ss = fs[i];
        float2 o0, o1;
        o0.x = a.x * cc - bb.x * ss;  o0.y = a.y * cc - bb.y * ss;
        o1.x = a.x * ss + bb.x * cc;  o1.y = a.y * ss + bb.y * cc;
        if (kind == 0) {
            g_q[b0 * DIM + er]     = o0.x;  g_q[b1 * DIM + er]     = o0.y;
            g_q[b0 * DIM + er + 1] = o1.x;  g_q[b1 * DIM + er + 1] = o1.y;
        } else {
            g_kn[b0 * 1024 + er]     = o0.x;  g_kn[b1 * 1024 + er]     = o0.y;
            g_kn[b0 * 1024 + er + 1] = o1.x;  g_kn[b1 * 1024 + er + 1] = o1.y;
        }
    }
}

// =================================================================
// Stage 2: attention v4.  One CTA per (batch, kv_head): 128 CTAs,
// 512 threads.  Max-free softmax.  2 barriers per tile:
//   A: warp = 4 keys x 8 dim-octets (conflict-free K reads);
//      in-warp shuffle reduce -> p = exp(s) -> p_sh.  No spart.
//   C: thread (g8=key-octet, j) -> 4 heads x 8 keys, V read once.
// K padded (stride 33 f4), V unpadded (stride 32 f4).
// Triple-buffered 64-key tiles; prefetch issued right after bar1.
// =================================================================
#define TILE     64
#define NTILES   (MSL / TILE)
#define KROW_F4  33
#define KTILE_F4 (TILE * KROW_F4)   // 2112
#define VTILE_F4 (TILE * 32)        // 2048
#define NBUF     3

__global__ __launch_bounds__(512, 1)
void attn_kernel(const float* __restrict__ cache_k,
                 const float* __restrict__ cache_v)
{
    extern __shared__ float4 sm4[];
    float4* Kbuf = sm4;                                   // 3 * 2112
    float4* Vbuf = sm4 + NBUF * KTILE_F4;                 // 3 * 2048
    float4* q4   = sm4 + NBUF * (KTILE_F4 + VTILE_F4);    // 128 (Q, pre-scaled)
    float*  fp      = (float*)(q4 + 128);
    float*  p_sh    = fp;                    // 256: [h][t]
    float*  red4    = fp + 256;              // 64: [warp][h]
    float*  linv_sh = fp + 320;              // 4
    float2* oacc    = (float2*)Kbuf;         // epilogue overlay: [ks][h][j] (16KB)

    const int tid  = threadIdx.x;
    const int b    = blockIdx.x >> 3;
    const int kv   = blockIdx.x & 7;
    const int lane = tid & 31;
    const int warp = tid >> 5;               // 0..15
    const int kk4  = lane & 3;               // key within warp's 4
    const int oo   = lane >> 2;              // dim octet 0..7
    const int g8   = tid >> 6;               // phase-C key octet
    const int t64  = tid & 63;               // phase-C column (float2)

    const float scale = 0.08838834764831845f;   // 1/sqrt(128)

    // load this CTA's 4 q heads (pre-scaled) into smem
    if (tid < 128) {
        int hh = tid >> 5, d4 = tid & 31;
        float4 qv = ((const float4*)g_q)[b * 1024 + (kv * 4 + hh) * 32 + d4];
        qv.x *= scale; qv.y *= scale; qv.z *= scale; qv.w *= scale;
        q4[hh * 32 + d4] = qv;
    }

    const float4* Ksrc = (const float4*)cache_k + ((size_t)b * MSL * NKV + kv) * 32;
    const float4* Vsrc = (const float4*)cache_v + ((size_t)b * MSL * NKV + kv) * 32;

    auto issue_tile = [&](int tile, int buf) {
        int pos0 = tile * TILE;
        float4* Kd = Kbuf + buf * KTILE_F4;
        float4* Vd = Vbuf + buf * VTILE_F4;
#pragma unroll
        for (int i = 0; i < 4; ++i) {
            int lin = (i << 9) + tid;            // 0..2047
            int row = lin >> 5, col = lin & 31;
            size_t g = (size_t)(pos0 + row) * 256 + col;
            cp_async16(&Kd[row * KROW_F4 + col], &Ksrc[g]);
            cp_async16(&Vd[row * 32 + col],      &Vsrc[g]);
        }
    };

    issue_tile(0, 0);
    cp_commit();
    issue_tile(1, 1);
    cp_commit();

    float lacc0 = 0.f, lacc1 = 0.f, lacc2 = 0.f, lacc3 = 0.f;
    ull pv[4];
#pragma unroll
    for (int h = 0; h < 4; ++h) pv[h] = 0ull;

    for (int tile = 0; tile < NTILES; ++tile) {
        const int buf = tile % NBUF;
        if (tile + 1 < NTILES) {
            asm volatile("cp.async.wait_group 1;" ::: "memory");
        } else {
            asm volatile("cp.async.wait_group 0;" ::: "memory");
        }
        __syncthreads();    // bar1: data(tile) visible; C(tile-1) done

        float4* Kc = Kbuf + buf * KTILE_F4;
        float4* Vc = Vbuf + buf * VTILE_F4;

        if (tile == NTILES - 1) {
            // replace position 4095 with the new roped token
            if (tid < 32)
                Kc[63 * KROW_F4 + tid] = ((const float4*)g_kn)[b * 256 + kv * 32 + tid];
            else if (tid < 64)
                Vc[63 * 32 + (tid - 32)] = ((const float4*)g_vn)[b * 256 + kv * 32 + (tid - 32)];
            __syncthreads();
        }

        // prefetch tile+2 into slot (tile+2)%3 == (tile-1)%3 (free since bar1)
        if (tile + 2 < NTILES) {
            issue_tile(tile + 2, (tile + 2) % NBUF);
            cp_commit();
        }

        // ---- Phase A: scores, in-warp reduced; conflict-free K reads ----
        {
            const float4* Krow = Kc + ((warp << 2) + kk4) * KROW_F4 + (oo << 2);
            const float4* Qb   = q4 + (oo << 2);
            ull s0 = 0, s1 = 0, s2 = 0, s3 = 0;
#pragma unroll
            for (int i = 0; i < 4; ++i) {
                ulonglong2 kw = *(const ulonglong2*)&Krow[i];
                ulonglong2 q0 = *(const ulonglong2*)&Qb[0 * 32 + i];   // broadcast
                ulonglong2 q1 = *(const ulonglong2*)&Qb[1 * 32 + i];
                ulonglong2 q2 = *(const ulonglong2*)&Qb[2 * 32 + i];
                ulonglong2 q3 = *(const ulonglong2*)&Qb[3 * 32 + i];
                s0 = f2fma(q0.x, kw.x, s0);  s0 = f2fma(q0.y, kw.y, s0);
                s1 = f2fma(q1.x, kw.x, s1);  s1 = f2fma(q1.y, kw.y, s1);
                s2 = f2fma(q2.x, kw.x, s2);  s2 = f2fma(q2.y, kw.y, s2);
                s3 = f2fma(q3.x, kw.x, s3);  s3 = f2fma(q3.y, kw.y, s3);
            }
            // reduce over the 8 dim-octets (lane stride 4)
#pragma unroll
            for (int off = 4; off <= 16; off <<= 1) {
                s0 = f2add(s0, __shfl_xor_sync(0xffffffffu, s0, off));
                s1 = f2add(s1, __shfl_xor_sync(0xffffffffu, s1, off));
                s2 = f2add(s2, __shfl_xor_sync(0xffffffffu, s2, off));
                s3 = f2add(s3, __shfl_xor_sync(0xffffffffu, s3, off));
            }
            if (lane < 4) {
                int key = (warp << 2) + lane;
                float2 a0 = unp2(s0), a1 = unp2(s1), a2 = unp2(s2), a3 = unp2(s3);
                float p0 = __expf(a0.x + a0.y);
                float p1 = __expf(a1.x + a1.y);
                float p2 = __expf(a2.x + a2.y);
                float p3 = __expf(a3.x + a3.y);
                p_sh[0 * 64 + key] = p0;  lacc0 += p0;
                p_sh[1 * 64 + key] = p1;  lacc1 += p1;
                p_sh[2 * 64 + key] = p2;  lacc2 += p2;
                p_sh[3 * 64 + key] = p3;  lacc3 += p3;
            }
        }
        __syncthreads();    // bar2: p_sh ready

        // ---- Phase C: PV; V read once; thread (g8, j): 8 keys x 4 heads ----
        {
            const ull* Vu = (const ull*)Vc;      // float2 units, row stride 64
            int t0 = g8 << 3;
            ull v[8];
#pragma unroll
            for (int k = 0; k < 8; ++k)
                v[k] = Vu[(t0 + k) * 64 + t64];
#pragma unroll
            for (int h = 0; h < 4; ++h) {
                float4 pa = *(const float4*)&p_sh[(h << 6) + t0];      // broadcast
                float4 pb = *(const float4*)&p_sh[(h << 6) + t0 + 4];
                pv[h] = f2fma(pack2(pa.x, pa.x), v[0], pv[h]);
                pv[h] = f2fma(pack2(pa.y, pa.y), v[1], pv[h]);
                pv[h] = f2fma(pack2(pa.z, pa.z), v[2], pv[h]);
                pv[h] = f2fma(pack2(pa.w, pa.w), v[3], pv[h]);
                pv[h] = f2fma(pack2(pb.x, pb.x), v[4], pv[h]);
                pv[h] = f2fma(pack2(pb.y, pb.y), v[5], pv[h]);
                pv[h] = f2fma(pack2(pb.z, pb.z), v[6], pv[h]);
                pv[h] = f2fma(pack2(pb.w, pb.w), v[7], pv[h]);
            }
        }
    }

    // ---- epilogue ----
    __syncthreads();        // all phase C done; Kbuf free for oacc overlay
    // l reduction: lanes 0-3 of each warp hold per-key-column partials
    {
        float w0 = lacc0, w1 = lacc1, w2 = lacc2, w3 = lacc3;
#pragma unroll
        for (int off = 1; off <= 2; off <<= 1) {
            w0 += __shfl_xor_sync(0xffffffffu, w0, off);
            w1 += __shfl_xor_sync(0xffffffffu, w1, off);
            w2 += __shfl_xor_sync(0xffffffffu, w2, off);
            w3 += __shfl_xor_sync(0xffffffffu, w3, off);
        }
        if (lane == 0) {
            red4[warp * 4 + 0] = w0;
            red4[warp * 4 + 1] = w1;
            red4[warp * 4 + 2] = w2;
            red4[warp * 4 + 3] = w3;
        }
    }
    // pv partials to smem: oacc[ks*256 + h*64 + j] (float2 units)
#pragma unroll
    for (int h = 0; h < 4; ++h)
        oacc[(g8 << 8) + (h << 6) + t64] = unp2(pv[h]);
    __syncthreads();
    if (tid < 4) {
        float l = 0.f;
#pragma unroll
        for (int w = 0; w < 16; ++w) l += red4[w * 4 + tid];
        linv_sh[tid] = 1.f / l;
    }
    __syncthreads();
    if (tid < 256) {
        int h = tid >> 6, j = tid & 63;
        float2 o = make_float2(0.f, 0.f);
#pragma unroll
        for (int ks = 0; ks < 8; ++ks) {
            float2 t = oacc[(ks << 8) + (h << 6) + j];
            o.x += t.x;  o.y += t.y;
        }
        float inv = linv_sh[h];
        ((float2*)g_ao)[b * (DIM / 2) + (kv * 4 + h) * 64 + j] =
            make_float2(o.x * inv, o.y * inv);
    }
}

// =================================================================
// Stage 3: output projection (wo, 4096 rows / 16 = 256 blocks).
// =================================================================
__global__ __launch_bounds__(128, 3)
void o_kernel(const float* __restrict__ wo, float* __restrict__ out)
{
    extern __shared__ float4 xsm[];
    float4* lo = xsm;
    float4* hi = xsm + 2048;
    const int warp = threadIdx.x >> 5;
    const int lane = threadIdx.x & 31;
    const int e0   = blockIdx.x * 16 + warp * 4;

    ull acc[32];
    gemv_r4(g_ao, wo + (size_t)e0 * DIM, lo, hi, acc);

    int r  = lane >> 3;
    int bp = lane & 7;
    int er = e0 + r;
    float2 v = unp2(acc[0]);
    out[(2 * bp)     * DIM + er] = v.x;
    out[(2 * bp + 1) * DIM + er] = v.y;
}

// =================================================================
// Launch
// =================================================================
#define GEMV_SMEM 65536
#define ATTN_SMEM ((NBUF * (KTILE_F4 + VTILE_F4) + 128) * 16 + 324 * 4)  // 203,024 B

extern "C" void kernel_launch(void* const* d_in, const int* in_sizes, int n_in,
                              void* d_out, int out_size)
{
    const float* x  = (const float*)d_in[0];
    const float* wq = (const float*)d_in[1];
    const float* wk = (const float*)d_in[2];
    const float* wv = (const float*)d_in[3];
    const float* wo = (const float*)d_in[4];
    const float* ck = (const float*)d_in[5];
    const float* cv = (const float*)d_in[6];
    const float* fc = (const float*)d_in[7];
    const float* fs = (const float*)d_in[8];
    float* out = (float*)d_out;

    cudaFuncSetAttribute(qkv_kernel,  cudaFuncAttributeMaxDynamicSharedMemorySize, GEMV_SMEM);
    cudaFuncSetAttribute(o_kernel,    cudaFuncAttributeMaxDynamicSharedMemorySize, GEMV_SMEM);
    cudaFuncSetAttribute(attn_kernel, cudaFuncAttributeMaxDynamicSharedMemorySize, ATTN_SMEM);

    qkv_kernel<<<384, 128, GEMV_SMEM>>>(x, wq, wk, wv, fc, fs);
    attn_kernel<<<128, 512, ATTN_SMEM>>>(ck, cv);
    o_kernel<<<256, 128, GEMV_SMEM>>>(wo, out);
}